// round 17
// baseline (speedup 1.0000x reference)
#include <cuda_runtime.h>
#include <cuda_fp16.h>
#include <math.h>
#include <stdint.h>

#define B_   4096
#define T_   32
#define H_   512
#define NG   2048   // 4*H
#define EMB_ 64
#define V_   256
#define O_   64

#define WSCALE 16.0f
#define INV_WSCALE 0.0625f

// ---------------- persistent scratch ----------------
__device__ float d_table[2][V_][NG];            // per-char gate preactivation (+biases), mma-column layout
__device__ __half d_w16[2][NG][H_];             // (W*16) fp16, rows = mma columns, K contiguous
__device__ __half d_hx[2][2][B_ * H_];          // [dir][0] final h for the head
__device__ float d_c[2][B_ * H_];               // cell state, thread-private coalesced layout

// column n (0..2047) -> torch gate row j
__device__ __forceinline__ int jmap2(int n) {
    int gate = (((n >> 3) & 1) << 1) | (n & 1);
    int u    = ((n >> 4) << 2) | ((n >> 1) & 3);
    return gate * H_ + u;
}
__device__ __forceinline__ float sig_f(float x) {
    return __fdividef(1.0f, 1.0f + __expf(-x));
}
__device__ __forceinline__ float tanh_f(float x) {
    return __fdividef(2.0f, 1.0f + __expf(-2.0f * x)) - 1.0f;
}

// ---------------- PTX helpers (plain-target safe) ----------------
__device__ __forceinline__ uint32_t smem_u32(const void* p) {
    uint32_t a;
    asm("{ .reg .u64 t; cvta.to.shared.u64 t, %1; cvt.u32.u64 %0, t; }" : "=r"(a) : "l"(p));
    return a;
}
__device__ __forceinline__ void cp16(uint32_t saddr, const void* g) {
    asm volatile("cp.async.cg.shared.global [%0], [%1], 16;" :: "r"(saddr), "l"(g));
}
#define CP_COMMIT() asm volatile("cp.async.commit_group;" ::: "memory")
#define CP_WAIT(n)  asm volatile("cp.async.wait_group %0;" :: "n"(n) : "memory")

__device__ __forceinline__ void ldsm_x4(uint32_t addr, uint32_t* r) {
    asm volatile("ldmatrix.sync.aligned.m8n8.x4.shared.b16 {%0,%1,%2,%3}, [%4];"
        : "=r"(r[0]), "=r"(r[1]), "=r"(r[2]), "=r"(r[3]) : "r"(addr));
}
__device__ __forceinline__ void mma_f16(float* c, const uint32_t* a, uint32_t b0, uint32_t b1) {
    asm volatile("mma.sync.aligned.m16n8k16.row.col.f32.f16.f16.f32 "
        "{%0,%1,%2,%3}, {%4,%5,%6,%7}, {%8,%9}, {%0,%1,%2,%3};"
        : "+f"(c[0]), "+f"(c[1]), "+f"(c[2]), "+f"(c[3])
        : "r"(a[0]), "r"(a[1]), "r"(a[2]), "r"(a[3]), "r"(b0), "r"(b1));
}

// 128B-row tile swizzle (W tiles): 16B chunk ^= row&7
__device__ __forceinline__ uint32_t swzoff(int row, int cb) {
    uint32_t off = (uint32_t)(row * 128 + cb);
    return off ^ (uint32_t)((row & 7) << 4);
}

// ---------------- SMEM layout ----------------
// hbuf: 2 x (64 rows x 1024B) = 131072; chunk-swizzled per 128B block: ch ^= row&7
// W stages: 3 x (256 rows x 128B) = 98304
#define HBUF_SZ   65536
#define OFF_H(b)  ((b) * HBUF_SZ)
#define WTILE_SZ  32768
#define OFF_W(s)  (2 * HBUF_SZ + (s) * WTILE_SZ)
#define SMEM_TOTAL (2 * HBUF_SZ + 3 * WTILE_SZ)   // 229376

// ---------------- one-off precompute ----------------
__global__ void build_table(const float* __restrict__ emb,
                            const float* __restrict__ Wih1, const float* __restrict__ bih1, const float* __restrict__ bhh1,
                            const float* __restrict__ Wih2, const float* __restrict__ bih2, const float* __restrict__ bhh2) {
    int n   = blockIdx.x * 128 + threadIdx.x;
    int v   = blockIdx.y;
    int dir = blockIdx.z;
    const float* Wih = dir ? Wih2 : Wih1;
    const float* bi  = dir ? bih2 : bih1;
    const float* bh  = dir ? bhh2 : bhh1;
    int j = jmap2(n);
    float s = bi[j] + bh[j];
    const float* e = emb + v * EMB_;
    const float* w = Wih + j * EMB_;
#pragma unroll 16
    for (int k = 0; k < EMB_; k++) s += e[k] * w[k];
    d_table[dir][v][n] = s;
}

__global__ void build_wt(const float* __restrict__ Whh1, const float* __restrict__ Whh2) {
    int k   = blockIdx.x * 128 + threadIdx.x;
    int n   = blockIdx.y;
    int dir = blockIdx.z;
    const float* W = dir ? Whh2 : Whh1;
    d_w16[dir][n][k] = __float2half_rn(W[jmap2(n) * H_ + k] * WSCALE);
}

// ---------------- W stage: 256 rows x 64 K fp16 = 256 x 128B (256 threads) ----------------
__device__ __forceinline__ void stage_w(uint32_t sdst,
                                        const __half* __restrict__ src,
                                        int n0, int k0, int tid) {
#pragma unroll
    for (int j = 0; j < 8; j++) {
        int lin = tid + j * 256;              // 0..2047
        int row = lin >> 3;                   // 0..255
        int c   = lin & 7;
        cp16(sdst + swzoff(row, c * 16),
             (const char*)(src + (size_t)(n0 + row) * H_ + k0) + c * 16);
    }
}

// ---------------- persistent bidirectional LSTM: one CTA = 64 batch rows x 1 dir ----------------
__global__ void __launch_bounds__(256) lstm_persist(const int* __restrict__ x) {
    extern __shared__ __align__(1024) char sm[];
    const int band = blockIdx.x;          // 0..63
    const int dir  = blockIdx.z;
    const int bg0  = band * 64;           // global batch row base

    float* __restrict__ cst = d_c[dir];
    const __half* __restrict__ W = &d_w16[dir][0][0];

    const uint32_t sb = smem_u32(sm);
    const int tid  = threadIdx.x;
    const int wid  = tid >> 5;
    const int lane = tid & 31;
    const int wm   = wid >> 2;    // 0..1: 32-row band
    const int wn   = wid & 3;     // 0..3: 64-col band within 256-col tile
    const int g    = lane >> 2;
    const int tg   = lane & 3;
    const int lrow  = lane & 15;
    const int lhalf = lane >> 4;

    // zero h(0) buffer
    {
        uint4 z = make_uint4(0, 0, 0, 0);
        for (int i4 = tid; i4 < HBUF_SZ / 16; i4 += 256)
            ((uint4*)sm)[i4] = z;
    }

    // A-frag addressing into hbuf: rows wm*32 + i*16 + lrow; per-kk chunk cc = kk*2 + lhalf
    uint32_t rowbaseA[2];
    uint32_t rxA[2];
#pragma unroll
    for (int i = 0; i < 2; i++) {
        int r = wm * 32 + i * 16 + lrow;
        rowbaseA[i] = (uint32_t)(r * 1024);
        rxA[i]      = (uint32_t)(r & 7);
    }
    // B-frag offsets within W tile (static per thread)
    uint32_t oB[4][4];
#pragma unroll
    for (int kk = 0; kk < 4; kk++) {
        const int kb = kk * 32 + lhalf * 16;
#pragma unroll
        for (int q = 0; q < 4; q++) oB[q][kk] = swzoff(wn * 64 + q * 16 + lrow, kb);
    }

    __syncthreads();   // hbuf zero visible

    // prologue: stage flattened m=0,1 (t=0, j=0, kt=0/1)
    stage_w(sb + OFF_W(0), W, 0, 0, tid);
    CP_COMMIT();
    stage_w(sb + OFF_W(1), W, 0, 64, tid);
    CP_COMMIT();

    float acc[2][8][4];
    const int MTOT = T_ * 64;   // 2048

    for (int m = 0; m < MTOT; m++) {
        const int kt = m & 7;
        const int j  = (m >> 3) & 7;
        const int t  = m >> 6;

        if (kt == 0) {
#pragma unroll
            for (int i = 0; i < 2; i++)
#pragma unroll
                for (int jj = 0; jj < 8; jj++)
#pragma unroll
                    for (int r = 0; r < 4; r++) acc[i][jj][r] = 0.f;
        }

        if (m < MTOT - 1) { CP_WAIT(1); } else { CP_WAIT(0); }
        __syncthreads();

        if (m + 2 < MTOT) {
            const int m2  = m + 2;
            const int n0s = ((m2 >> 3) & 7) << 8;
            const int k0s = (m2 & 7) << 6;
            stage_w(sb + OFF_W(m2 % 3), W, n0s, k0s, tid);
            CP_COMMIT();
        }

        const uint32_t baseA = sb + OFF_H(t & 1) + (uint32_t)(kt * 128);
        const uint32_t baseB = sb + OFF_W(m % 3);
#pragma unroll
        for (int kk = 0; kk < 4; kk++) {
            uint32_t af[2][4], bf4[4][4];
            const uint32_t cc = (uint32_t)(kk * 2 + lhalf);
#pragma unroll
            for (int i = 0; i < 2; i++)
                ldsm_x4(baseA + rowbaseA[i] + ((cc ^ rxA[i]) << 4), af[i]);
#pragma unroll
            for (int q = 0; q < 4; q++) ldsm_x4(baseB + oB[q][kk], bf4[q]);
#pragma unroll
            for (int i = 0; i < 2; i++)
#pragma unroll
                for (int q = 0; q < 4; q++)
#pragma unroll
                    for (int nb2 = 0; nb2 < 2; nb2++)
                        mma_f16(acc[i][q * 2 + nb2], af[i], bf4[q][nb2], bf4[q][nb2 + 2]);
        }

        if (kt == 7) {
            // ---------------- epilogue for n-tile j of step t ----------------
            const int tcol = dir ? (T_ - 1 - t) : t;
            char* hnext = sm + OFF_H((t + 1) & 1);

            int chv[2][2];
#pragma unroll
            for (int i = 0; i < 2; i++) {
                const int r0 = wm * 32 + i * 16 + g;
                chv[i][0] = x[(size_t)(bg0 + r0) * T_ + tcol];
                chv[i][1] = x[(size_t)(bg0 + r0 + 8) * T_ + tcol];
            }

            const int cbase = (((band * 8 + j) * 256 + tid) << 4);
            float cv[16];
            if (t == 0) {
#pragma unroll
                for (int q = 0; q < 16; q++) cv[q] = 0.f;
            } else {
#pragma unroll
                for (int q = 0; q < 4; q++) *(float4*)&cv[q * 4] = *(const float4*)&cst[cbase + q * 4];
            }

#pragma unroll
            for (int i = 0; i < 2; i++) {
                const int r0 = wm * 32 + i * 16 + g;
                const float* trow0 = &d_table[dir][chv[i][0]][j * 256];
                const float* trow1 = &d_table[dir][chv[i][1]][j * 256];
#pragma unroll
                for (int jj = 0; jj < 4; jj++) {
                    const int colIF = wn * 64 + jj * 16 + 2 * tg;
                    const int u_l   = (wn * 4 + jj) * 4 + tg;      // unit within tile 0..63
                    const int unit  = j * 64 + u_l;                 // global unit 0..511
                    const uint32_t ublk = (uint32_t)(unit >> 6) * 128 + (uint32_t)(unit & 7) * 2;
                    const uint32_t uch  = (uint32_t)((unit >> 3) & 7);
#pragma unroll
                    for (int half = 0; half < 2; half++) {
                        const float* trow = half ? trow1 : trow0;
                        const float2 tif = *(const float2*)&trow[colIF];
                        const float2 tgo = *(const float2*)&trow[colIF + 8];
                        float gi = fmaf(INV_WSCALE, acc[i][jj * 2 + 0][half * 2 + 0], tif.x);
                        float gf = fmaf(INV_WSCALE, acc[i][jj * 2 + 0][half * 2 + 1], tif.y);
                        float gg = fmaf(INV_WSCALE, acc[i][jj * 2 + 1][half * 2 + 0], tgo.x);
                        float go = fmaf(INV_WSCALE, acc[i][jj * 2 + 1][half * 2 + 1], tgo.y);
                        const int idx = i * 8 + jj * 2 + half;
                        float c_new = sig_f(gf) * cv[idx] + sig_f(gi) * tanh_f(gg);
                        cv[idx] = c_new;
                        const float hv = sig_f(go) * tanh_f(c_new);
                        const int rl = r0 + half * 8;               // local row 0..63
                        *(__half*)(hnext + rl * 1024 + ublk + ((uch ^ (uint32_t)(rl & 7)) << 4)) =
                            __float2half_rn(hv);
                    }
                }
            }
#pragma unroll
            for (int q = 0; q < 4; q++) *(float4*)&cst[cbase + q * 4] = *(const float4*)&cv[q * 4];
        }
    }

    // ---------------- copy final h (hbuf[0], since T_ even) to global for the head ----------------
    __syncthreads();
    {
        const char* hb = sm + OFF_H(T_ & 1);
        for (int c = tid; c < 4096; c += 256) {
            int row = c >> 6;
            int blk = (c >> 3) & 7;
            int ch  = c & 7;
            uint4 v = *(const uint4*)(hb + row * 1024 + blk * 128 + ((ch ^ (row & 7)) << 4));
            *(uint4*)((char*)&d_hx[dir][0][(size_t)(bg0 + row) * H_] + blk * 128 + ch * 16) = v;
        }
    }
}

// ---------------- classifier head + softmax (tiled: 32 rows / block) ----------------
#define HEAD_ROWS 32
#define HEAD_SMEM (HEAD_ROWS * 1024 * 2 + HEAD_ROWS * 66 * 4)   // 73984
__global__ void __launch_bounds__(256) head_kernel(const float* __restrict__ Wlin,
                                                   const float* __restrict__ blin,
                                                   float* __restrict__ out) {
    extern __shared__ char hsm[];
    __half* hrow = (__half*)hsm;                           // [32][1024]
    float*  lgs  = (float*)(hsm + HEAD_ROWS * 1024 * 2);   // [32][66]
    const int b0   = blockIdx.x * HEAD_ROWS;
    const int tid  = threadIdx.x;
    const int w    = tid >> 5;
    const int lane = tid & 31;

#pragma unroll
    for (int it = 0; it < 8; it++) {
        int idx = tid + it * 256;
        int r = idx >> 6;
        int c = idx & 63;
        *(uint4*)&hrow[r * 1024 + c * 8] =
            *(const uint4*)&d_hx[0][0][(size_t)(b0 + r) * H_ + c * 8];
        *(uint4*)&hrow[r * 1024 + 512 + c * 8] =
            *(const uint4*)&d_hx[1][0][(size_t)(b0 + r) * H_ + c * 8];
    }
    __syncthreads();

#pragma unroll
    for (int oo = 0; oo < 8; oo++) {
        const int o = w * 8 + oo;
        float4 wreg[8];
#pragma unroll
        for (int kk = 0; kk < 8; kk++)
            wreg[kk] = *(const float4*)&Wlin[o * 1024 + kk * 128 + lane * 4];
        const float bo = blin[o];
        for (int r = 0; r < HEAD_ROWS; r++) {
            float s = 0.f;
#pragma unroll
            for (int kk = 0; kk < 8; kk++) {
                const __half2* hp = (const __half2*)&hrow[r * 1024 + kk * 128 + lane * 4];
                float2 h01 = __half22float2(hp[0]);
                float2 h23 = __half22float2(hp[1]);
                s += wreg[kk].x * h01.x + wreg[kk].y * h01.y
                   + wreg[kk].z * h23.x + wreg[kk].w * h23.y;
            }
#pragma unroll
            for (int off = 16; off; off >>= 1) s += __shfl_down_sync(0xffffffffu, s, off);
            if (lane == 0) lgs[r * 66 + o] = s + bo;
        }
    }
    __syncthreads();

#pragma unroll
    for (int rr = 0; rr < 4; rr++) {
        const int r = w * 4 + rr;
        float v0 = lgs[r * 66 + lane];
        float v1 = lgs[r * 66 + 32 + lane];
        float m = fmaxf(v0, v1);
#pragma unroll
        for (int off = 16; off; off >>= 1) m = fmaxf(m, __shfl_xor_sync(0xffffffffu, m, off));
        float e0 = __expf(v0 - m), e1 = __expf(v1 - m);
        float s = e0 + e1;
#pragma unroll
        for (int off = 16; off; off >>= 1) s += __shfl_xor_sync(0xffffffffu, s, off);
        float inv = __fdividef(1.0f, s);
        out[(size_t)(b0 + r) * O_ + lane]      = e0 * inv;
        out[(size_t)(b0 + r) * O_ + 32 + lane] = e1 * inv;
    }
}

// ---------------- launch ----------------
extern "C" void kernel_launch(void* const* d_in, const int* in_sizes, int n_in,
                              void* d_out, int out_size) {
    const int*   x    = (const int*)d_in[0];
    const float* emb  = (const float*)d_in[2];
    const float* Wih1 = (const float*)d_in[3];
    const float* Whh1 = (const float*)d_in[4];
    const float* bih1 = (const float*)d_in[5];
    const float* bhh1 = (const float*)d_in[6];
    const float* Wih2 = (const float*)d_in[7];
    const float* Whh2 = (const float*)d_in[8];
    const float* bih2 = (const float*)d_in[9];
    const float* bhh2 = (const float*)d_in[10];
    const float* Wlin = (const float*)d_in[11];
    const float* blin = (const float*)d_in[12];
    float* out = (float*)d_out;

    cudaFuncSetAttribute(lstm_persist, cudaFuncAttributeMaxDynamicSharedMemorySize, SMEM_TOTAL);
    cudaFuncSetAttribute(head_kernel,  cudaFuncAttributeMaxDynamicSharedMemorySize, HEAD_SMEM);

    dim3 g1(NG / 128, V_, 2);
    build_table<<<g1, 128>>>(emb, Wih1, bih1, bhh1, Wih2, bih2, bhh2);
    dim3 g2(H_ / 128, NG, 2);
    build_wt<<<g2, 128>>>(Whh1, Whh2);

    dim3 gp(B_ / 64, 1, 2);   // 128 CTAs, 1/SM
    lstm_persist<<<gp, 256, SMEM_TOTAL>>>(x);

    head_kernel<<<B_ / HEAD_ROWS, 256, HEAD_SMEM>>>(Wlin, blin, out);
}